// round 2
// baseline (speedup 1.0000x reference)
#include <cuda_runtime.h>
#include <cuda_bf16.h>

#define CONV   49
#define PDIM   245          // 5*49: [W2_0 | W2_1 | W2_2 | B2 | root_w] columns
#define MAXN   25000
#define MAXE   50000
#define LRELU(v) ((v) > 0.0f ? (v) : 0.01f * (v))

// ---------------- device scratch (no allocations allowed) ----------------
__device__ float g_hcA[MAXN * CONV];
__device__ float g_hcB[MAXN * CONV];
__device__ float g_P  [MAXN * PDIM];
__device__ float g_agg[MAXN * CONV];   // aggregation, then reused as pre-BN buffer
__device__ float g_invd[MAXN];
__device__ float g_stats[2 * CONV];    // [sum | sumsq]
__device__ int   g_src[MAXE];
__device__ int   g_dst[MAXE];
__device__ int   g_is64;

// ---------------- edge-index dtype sniffing + decode ----------------
// If buffer is int64 (little-endian, values < 2^31), every odd int32 word of
// the first 1024 values is 0. If int32, those words are random node indices.
__global__ void k_sniff(const int* __restrict__ w, int nvals, int* flag) {
    if (threadIdx.x == 0 && blockIdx.x == 0) *flag = 1;
    __threadfence();
    int i = blockIdx.x * blockDim.x + threadIdx.x;
    if (i < nvals && w[2 * i + 1] != 0) atomicAnd(flag, 0);
}

__global__ void k_decode(const void* __restrict__ raw, const int* __restrict__ flag,
                         int* __restrict__ src, int* __restrict__ dst, int E) {
    int e = blockIdx.x * blockDim.x + threadIdx.x;
    if (e >= E) return;
    if (*flag) {
        const long long* p = (const long long*)raw;
        src[e] = (int)p[e];
        dst[e] = (int)p[E + e];
    } else {
        const int* p = (const int*)raw;
        src[e] = p[e];
        dst[e] = p[E + e];
    }
}

// ---------------- small utility kernels ----------------
__global__ void k_zero(float* p, int n) {
    int i = blockIdx.x * blockDim.x + threadIdx.x;
    if (i < n) p[i] = 0.0f;
}

__global__ void k_deg(const int* __restrict__ dst, float* __restrict__ deg, int E) {
    int e = blockIdx.x * blockDim.x + threadIdx.x;
    if (e < E) atomicAdd(&deg[dst[e]], 1.0f);
}

__global__ void k_invd(float* d, int N) {
    int n = blockIdx.x * blockDim.x + threadIdx.x;
    if (n < N) d[n] = 1.0f / fmaxf(d[n], 1.0f);
}

// ---------------- input projection: h = leaky_relu(x @ lin_w + lin_b) ----
__global__ __launch_bounds__(256) void k_proj(
    const float* __restrict__ x, const float* __restrict__ lin_w,
    const float* __restrict__ lin_b, float* __restrict__ h,
    float* __restrict__ jk, int N)
{
    __shared__ float sw[56 * CONV];
    int tid = threadIdx.y * 64 + threadIdx.x;
    for (int i = tid; i < 56 * CONV; i += 256) sw[i] = lin_w[i];
    __syncthreads();

    int n = blockIdx.x * 4 + threadIdx.y;
    int o = threadIdx.x;
    if (n >= N || o >= CONV) return;
    const float* xr = x + (long)n * 56;
    float acc = lin_b[o];
    #pragma unroll
    for (int i = 0; i < 56; i++) acc = fmaf(xr[i], sw[i * CONV + o], acc);
    acc = LRELU(acc);
    h[n * CONV + o]  = acc;
    jk[n * CONV + o] = acc;   // xs[0] contribution to JK sum
}

// ---------------- per-node projection GEMM: P = hc @ [W2_0|W2_1|W2_2|B2|root] ----
// C = A(N x 49) * B(49 x 245). Block tile: 32 nodes x 245 cols.
__global__ __launch_bounds__(256) void k_P(
    const float* __restrict__ hc,
    const float* __restrict__ w2,    // 3*2401 (this layer)
    const float* __restrict__ b2,    // 2401
    const float* __restrict__ rw,    // 2401
    float* __restrict__ P,
    float* __restrict__ agg, float* __restrict__ stats, int N)
{
    // piggyback: zero agg + stats for this layer (stream-ordered before k_edge/k_out)
    int gtid = blockIdx.x * blockDim.x + threadIdx.x;
    for (int i = gtid; i < N * CONV; i += gridDim.x * blockDim.x) agg[i] = 0.0f;
    if (gtid < 2 * CONV) stats[gtid] = 0.0f;

    extern __shared__ float smem[];
    float* sw = smem;               // 49 * 245
    float* sh = smem + 49 * PDIM;   // 32 * 49

    int tid = threadIdx.x;
    for (int idx = tid; idx < 49 * PDIM; idx += 256) {
        int i = idx / PDIM, j = idx % PDIM;
        int m = j / CONV, o = j % CONV;
        float v;
        if (m < 3)       v = w2[m * 2401 + i * CONV + o];
        else if (m == 3) v = b2[i * CONV + o];
        else             v = rw[i * CONV + o];
        sw[idx] = v;
    }
    int nb = blockIdx.x * 32;
    for (int idx = tid; idx < 32 * CONV; idx += 256) {
        int ln = idx / CONV, i = idx % CONV;
        int n = nb + ln;
        sh[idx] = (n < N) ? hc[n * CONV + i] : 0.0f;
    }
    __syncthreads();

    int j0 = tid & 127;
    int j1 = j0 + 128;
    int ybase = (tid >> 7) * 16;

    float acc0[16], acc1[16];
    #pragma unroll
    for (int y = 0; y < 16; y++) { acc0[y] = 0.0f; acc1[y] = 0.0f; }

    bool has1 = (j1 < PDIM);
    for (int i = 0; i < CONV; i++) {
        float w0 = sw[i * PDIM + j0];
        float w1 = has1 ? sw[i * PDIM + j1] : 0.0f;
        #pragma unroll
        for (int y = 0; y < 16; y++) {
            float hv = sh[(ybase + y) * CONV + i];
            acc0[y] = fmaf(hv, w0, acc0[y]);
            acc1[y] = fmaf(hv, w1, acc1[y]);
        }
    }
    #pragma unroll
    for (int y = 0; y < 16; y++) {
        int n = nb + ybase + y;
        if (n < N) {
            P[(long)n * PDIM + j0] = acc0[y];
            if (has1) P[(long)n * PDIM + j1] = acc1[y];
        }
    }
}

// ---------------- edge kernel: msg = sum_m t_m * P[src,m,:] + P[src,3,:]; scatter ----
__global__ __launch_bounds__(256) void k_edge(
    const int* __restrict__ srcv, const int* __restrict__ dstv,
    const float* __restrict__ ea,
    const float* __restrict__ w1, const float* __restrict__ b1,
    const float* __restrict__ P, float* __restrict__ agg, int E)
{
    int warp = (blockIdx.x * blockDim.x + threadIdx.x) >> 5;
    int lane = threadIdx.x & 31;
    if (warp >= E) return;
    int src = srcv[warp];
    int dst = dstv[warp];

    const float* a = ea + warp * 10;
    float t0 = b1[0], t1 = b1[1], t2 = b1[2];
    #pragma unroll
    for (int i = 0; i < 10; i++) {
        float v = a[i];
        t0 = fmaf(v, w1[i * 3 + 0], t0);
        t1 = fmaf(v, w1[i * 3 + 1], t1);
        t2 = fmaf(v, w1[i * 3 + 2], t2);
    }
    t0 = fmaxf(t0, 0.0f); t1 = fmaxf(t1, 0.0f); t2 = fmaxf(t2, 0.0f);

    const float* Ps = P + (long)src * PDIM;
    float* ag = agg + (long)dst * CONV;
    #pragma unroll
    for (int o = lane; o < CONV; o += 32) {
        float m = fmaf(t0, Ps[o],
                  fmaf(t1, Ps[49 + o],
                  fmaf(t2, Ps[98 + o], Ps[147 + o])));
        atomicAdd(&ag[o], m);
    }
}

// ---------------- out = agg*invd + root + bias; accumulate BN stats ----
__global__ __launch_bounds__(512) void k_out(
    float* __restrict__ agg, const float* __restrict__ P,
    const float* __restrict__ invd, const float* __restrict__ convb,
    float* __restrict__ stats, int N)
{
    __shared__ float s1[8][CONV];
    __shared__ float s2[8][CONV];
    int o = threadIdx.x;
    int n = blockIdx.x * 8 + threadIdx.y;
    float v = 0.0f;
    bool act = (o < CONV && n < N);
    if (act) {
        v = fmaf(agg[n * CONV + o], invd[n], P[(long)n * PDIM + 196 + o] + convb[o]);
        agg[n * CONV + o] = v;   // reuse agg as pre-BN buffer
    }
    if (o < CONV) { s1[threadIdx.y][o] = act ? v : 0.0f; s2[threadIdx.y][o] = act ? v * v : 0.0f; }
    __syncthreads();
    if (threadIdx.y == 0 && o < CONV) {
        float a = 0.0f, b = 0.0f;
        #pragma unroll
        for (int y = 0; y < 8; y++) { a += s1[y][o]; b += s2[y][o]; }
        atomicAdd(&stats[o], a);
        atomicAdd(&stats[CONV + o], b);
    }
}

// ---------------- BN + leaky_relu; write next hc; accumulate JK ----
__global__ __launch_bounds__(256) void k_apply(
    const float* __restrict__ pre, const float* __restrict__ stats,
    const float* __restrict__ gamma, const float* __restrict__ beta,
    float* __restrict__ hc_out, float* __restrict__ jk, int N)
{
    int idx = blockIdx.x * blockDim.x + threadIdx.x;
    if (idx >= N * CONV) return;
    int o = idx % CONV;
    float invN = 1.0f / (float)N;
    float mu = stats[o] * invN;
    float var = stats[CONV + o] * invN - mu * mu;
    float sc = gamma[o] * rsqrtf(var + 1e-5f);
    float y = (pre[idx] - mu) * sc + beta[o];
    y = LRELU(y);
    hc_out[idx] = y;
    jk[idx] += y;
}

// ---------------------------------------------------------------------------
extern "C" void kernel_launch(void* const* d_in, const int* in_sizes, int n_in,
                              void* d_out, int out_size)
{
    const float* x     = (const float*)d_in[0];
    const void*  ei    = d_in[1];                 // int32 or int64 — sniffed on device
    const float* ea    = (const float*)d_in[2];
    const float* lin_w = (const float*)d_in[3];
    const float* lin_b = (const float*)d_in[4];
    const float* w1    = (const float*)d_in[5];   // (4,10,3)
    const float* b1    = (const float*)d_in[6];   // (4,3)
    const float* w2    = (const float*)d_in[7];   // (4,3,2401)
    const float* b2    = (const float*)d_in[8];   // (4,2401)
    const float* rw    = (const float*)d_in[9];   // (4,49,49)
    const float* cb    = (const float*)d_in[10];  // (4,49)
    const float* gam   = (const float*)d_in[11];  // (4,49)
    const float* bet   = (const float*)d_in[12];  // (4,49)
    float* jk = (float*)d_out;

    int N = in_sizes[0] / 56;
    int E = in_sizes[2] / 10;

    float *hcA, *hcB, *P, *agg, *invd, *stats;
    int *srcv, *dstv, *is64;
    cudaGetSymbolAddress((void**)&hcA,  g_hcA);
    cudaGetSymbolAddress((void**)&hcB,  g_hcB);
    cudaGetSymbolAddress((void**)&P,    g_P);
    cudaGetSymbolAddress((void**)&agg,  g_agg);
    cudaGetSymbolAddress((void**)&invd, g_invd);
    cudaGetSymbolAddress((void**)&stats,g_stats);
    cudaGetSymbolAddress((void**)&srcv, g_src);
    cudaGetSymbolAddress((void**)&dstv, g_dst);
    cudaGetSymbolAddress((void**)&is64, g_is64);

    int smemP = (49 * PDIM + 32 * CONV) * sizeof(float);  // ~54.3 KB
    cudaFuncSetAttribute(k_P, cudaFuncAttributeMaxDynamicSharedMemorySize, smemP);

    // decode edge indices (dtype-agnostic)
    int nsniff = (2 * E < 2048 ? 2 * E : 2048) / 2;   // #values whose high word we test
    k_sniff<<<(nsniff + 255) / 256, 256>>>((const int*)ei, nsniff, is64);
    k_decode<<<(E + 255) / 256, 256>>>(ei, is64, srcv, dstv, E);

    // degree -> inverse denom
    k_zero<<<(N + 255) / 256, 256>>>(invd, N);
    k_deg<<<(E + 255) / 256, 256>>>(dstv, invd, E);
    k_invd<<<(N + 255) / 256, 256>>>(invd, N);

    // input projection, JK init
    {
        dim3 b(64, 4);
        k_proj<<<(N + 3) / 4, b>>>(x, lin_w, lin_b, hcA, jk, N);
    }

    // NOTE: layer 3's output is never used in the JK sum (xs[0..3]) -> skip it.
    float* hin = hcA;
    float* hout = hcB;
    for (int l = 0; l < 3; l++) {
        k_P<<<(N + 31) / 32, 256, smemP>>>(hin,
            w2 + (long)l * 3 * 2401, b2 + (long)l * 2401, rw + (long)l * 2401,
            P, agg, stats, N);
        k_edge<<<(E + 7) / 8, 256>>>(srcv, dstv, ea, w1 + l * 30, b1 + l * 3, P, agg, E);
        {
            dim3 b(64, 8);
            k_out<<<(N + 7) / 8, b>>>(agg, P, invd, cb + l * CONV, stats, N);
        }
        k_apply<<<(N * CONV + 255) / 256, 256>>>(agg, stats, gam + l * CONV,
                                                 bet + l * CONV, hout, jk, N);
        float* tmp = hin; hin = hout; hout = tmp;
    }
}

// round 3
// speedup vs baseline: 1.0549x; 1.0549x over previous
#include <cuda_runtime.h>
#include <cuda_bf16.h>

#define TPB    256
#define CONV   49
#define PDIM   245          // 5*49: [W2_0 | W2_1 | W2_2 | B2 | root_w]
#define MAXN   25000
#define MAXE   50000
#define NTILE  32
#define LRELU(v) ((v) > 0.0f ? (v) : 0.01f * (v))

// smem layout (floats): sw[49*245] | sh[32*49] | sbn[98]
#define SMEM_FLOATS (49 * PDIM + NTILE * CONV + 2 * CONV)

// ---------------- device scratch ----------------
__device__ float g_hcA [MAXN * CONV];     // proj output (layer-0 input)
__device__ float g_P   [MAXN * PDIM];
__device__ float g_aggA[MAXN * CONV];
__device__ float g_aggB[MAXN * CONV];
__device__ float g_invd[MAXN];            // deg, then 1/max(deg,1)
__device__ float g_stats[2 * 2 * CONV];   // two ping-pong [sum(49)|sumsq(49)]
__device__ int   g_src[MAXE];
__device__ int   g_dst[MAXE];
__device__ int   g_is64;
__device__ unsigned g_bar_count = 0;
__device__ unsigned g_bar_gen   = 0;

// ---------------- grid-wide barrier (co-residency guaranteed by host) ----
__device__ __forceinline__ void grid_sync() {
    __syncthreads();
    if (threadIdx.x == 0) {
        __threadfence();
        unsigned gen = *(volatile unsigned*)&g_bar_gen;
        unsigned t = atomicAdd(&g_bar_count, 1u);
        if (t == gridDim.x - 1) {
            g_bar_count = 0;
            __threadfence();
            *(volatile unsigned*)&g_bar_gen = gen + 1;
        } else {
            while (*(volatile unsigned*)&g_bar_gen == gen) __nanosleep(64);
        }
        __threadfence();
    }
    __syncthreads();
}

// ---------------- the whole model in one kernel ----------------
__global__ __launch_bounds__(TPB) void k_fused(
    const float* __restrict__ x, const void* __restrict__ ei,
    const float* __restrict__ ea,
    const float* __restrict__ lin_w, const float* __restrict__ lin_b,
    const float* __restrict__ w1,  const float* __restrict__ b1,
    const float* __restrict__ w2,  const float* __restrict__ b2,
    const float* __restrict__ rw,  const float* __restrict__ cb,
    const float* __restrict__ gam, const float* __restrict__ bet,
    float* __restrict__ jk, int N, int E)
{
    extern __shared__ float smem[];
    float* sw  = smem;
    float* sh  = smem + 49 * PDIM;
    float* sbn = sh + NTILE * CONV;

    const int tid  = threadIdx.x;
    const int gtid = blockIdx.x * TPB + tid;
    const int gsz  = gridDim.x * TPB;

    // ===== Phase A: dtype sniff (block 0) + zero degree =====
    {
        int local_ok = 1;                       // "looks like int64"
        if (blockIdx.x == 0) {
            const int* w = (const int*)ei;
            int nv = (E < 1024) ? E : 1024;
            for (int i = tid; i < nv; i += TPB)
                if (w[2 * i + 1] != 0) local_ok = 0;
        }
        int all_ok = __syncthreads_and(local_ok);
        if (blockIdx.x == 0 && tid == 0) g_is64 = all_ok;
        for (int n = gtid; n < N; n += gsz) g_invd[n] = 0.0f;
    }
    grid_sync();

    // ===== Phase B: decode edges + degree atomics =====
    {
        int is64 = g_is64;
        if (is64) {
            const long long* p = (const long long*)ei;
            for (int e = gtid; e < E; e += gsz) {
                int s = (int)p[e], d = (int)p[E + e];
                g_src[e] = s; g_dst[e] = d;
                atomicAdd(&g_invd[d], 1.0f);
            }
        } else {
            const int* p = (const int*)ei;
            for (int e = gtid; e < E; e += gsz) {
                int s = p[e], d = p[E + e];
                g_src[e] = s; g_dst[e] = d;
                atomicAdd(&g_invd[d], 1.0f);
            }
        }
    }
    grid_sync();

    // ===== Phase C: invd + input projection (h, jk init) =====
    {
        for (int n = gtid; n < N; n += gsz)
            g_invd[n] = 1.0f / fmaxf(g_invd[n], 1.0f);
        for (int i = tid; i < 56 * CONV; i += TPB) sw[i] = lin_w[i];
        __syncthreads();
        int o = tid & 63, r = tid >> 6;           // 4 nodes x 64 lanes
        for (int nb = blockIdx.x * 4; nb < N; nb += gridDim.x * 4) {
            int n = nb + r;
            if (n < N && o < CONV) {
                const float* xr = x + (long)n * 56;
                float acc = lin_b[o];
                #pragma unroll
                for (int i = 0; i < 56; i++)
                    acc = fmaf(xr[i], sw[i * CONV + o], acc);
                acc = LRELU(acc);
                g_hcA[n * CONV + o] = acc;
                jk[n * CONV + o]   = acc;
            }
        }
    }
    grid_sync();

    const int TILES = (N + NTILE - 1) / NTILE;

    for (int l = 0; l < 3; l++) {
        float* aggNew   = (l & 1) ? g_aggB : g_aggA;
        float* aggOld   = (l & 1) ? g_aggA : g_aggB;
        float* statsNew = g_stats + (l & 1) * 98;
        float* statsOld = g_stats + ((l + 1) & 1) * 98;
        const float* w2l = w2 + (long)l * 3 * 2401;
        const float* b2l = b2 + (long)l * 2401;
        const float* rwl = rw + (long)l * 2401;

        // ===== Phase D: P-GEMM (with fused BN+lrelu+JK on input tile) =====
        {
            // combined weights -> smem
            for (int idx = tid; idx < 49 * PDIM; idx += TPB) {
                int i = idx / PDIM, j = idx % PDIM;
                int m = j / CONV, o = j % CONV;
                float v;
                if (m < 3)       v = w2l[m * 2401 + i * CONV + o];
                else if (m == 3) v = b2l[i * CONV + o];
                else             v = rwl[i * CONV + o];
                sw[idx] = v;
            }
            // BN coefficients for layer l-1 output
            if (l > 0 && tid < CONV) {
                float invN = 1.0f / (float)N;
                float mu  = statsOld[tid] * invN;
                float var = statsOld[CONV + tid] * invN - mu * mu;
                float sc  = gam[(l - 1) * CONV + tid] * rsqrtf(var + 1e-5f);
                sbn[tid]        = sc;
                sbn[CONV + tid] = bet[(l - 1) * CONV + tid] - mu * sc;
            }
            if (blockIdx.x == 0 && tid < 98) statsNew[tid] = 0.0f;
            for (int i = gtid; i < N * CONV; i += gsz) aggNew[i] = 0.0f;
            __syncthreads();

            int j0 = tid & 127;
            int j1 = j0 + 128;
            bool has1 = (j1 < PDIM);
            int ybase = (tid >> 7) * 16;

            for (int tile = blockIdx.x; tile < TILES; tile += gridDim.x) {
                int nb = tile * NTILE;
                // load tile (apply BN+lrelu for l>0; also accumulate JK once)
                for (int idx = tid; idx < NTILE * CONV; idx += TPB) {
                    int ln = idx / CONV, i = idx % CONV;
                    int n = nb + ln;
                    float y = 0.0f;
                    if (n < N) {
                        if (l == 0) {
                            y = g_hcA[n * CONV + i];
                        } else {
                            float pre = aggOld[n * CONV + i];
                            y = pre * sbn[i] + sbn[CONV + i];
                            y = LRELU(y);
                            jk[n * CONV + i] += y;
                        }
                    }
                    sh[idx] = y;
                }
                __syncthreads();

                float acc0[16], acc1[16];
                #pragma unroll
                for (int y = 0; y < 16; y++) { acc0[y] = 0.0f; acc1[y] = 0.0f; }
                for (int i = 0; i < CONV; i++) {
                    float w0 = sw[i * PDIM + j0];
                    float wv1 = has1 ? sw[i * PDIM + j1] : 0.0f;
                    #pragma unroll
                    for (int y = 0; y < 16; y++) {
                        float hv = sh[(ybase + y) * CONV + i];
                        acc0[y] = fmaf(hv, w0, acc0[y]);
                        acc1[y] = fmaf(hv, wv1, acc1[y]);
                    }
                }
                #pragma unroll
                for (int y = 0; y < 16; y++) {
                    int n = nb + ybase + y;
                    if (n < N) {
                        g_P[(long)n * PDIM + j0] = acc0[y];
                        if (has1) g_P[(long)n * PDIM + j1] = acc1[y];
                    }
                }
                __syncthreads();   // protect sh before next tile
            }
        }
        grid_sync();

        // ===== Phase E: edge messages + scatter =====
        {
            // edge-MLP weights to smem
            if (tid < 30) sw[tid] = w1[l * 30 + tid];
            if (tid < 3)  sw[32 + tid] = b1[l * 3 + tid];
            __syncthreads();
            int warp = (blockIdx.x * TPB + tid) >> 5;
            int lane = tid & 31;
            int nwarp = gsz >> 5;
            for (int e = warp; e < E; e += nwarp) {
                int src = g_src[e], dst = g_dst[e];
                const float* a = ea + (long)e * 10;
                float t0 = sw[32], t1 = sw[33], t2 = sw[34];
                #pragma unroll
                for (int i = 0; i < 10; i++) {
                    float v = a[i];
                    t0 = fmaf(v, sw[i * 3 + 0], t0);
                    t1 = fmaf(v, sw[i * 3 + 1], t1);
                    t2 = fmaf(v, sw[i * 3 + 2], t2);
                }
                t0 = fmaxf(t0, 0.0f); t1 = fmaxf(t1, 0.0f); t2 = fmaxf(t2, 0.0f);
                const float* Ps = g_P + (long)src * PDIM;
                float* ag = aggNew + (long)dst * CONV;
                float m0 = fmaf(t0, Ps[lane],
                           fmaf(t1, Ps[49 + lane],
                           fmaf(t2, Ps[98 + lane], Ps[147 + lane])));
                atomicAdd(&ag[lane], m0);
                int o2 = lane + 32;
                if (o2 < CONV) {
                    float m1 = fmaf(t0, Ps[o2],
                               fmaf(t1, Ps[49 + o2],
                               fmaf(t2, Ps[98 + o2], Ps[147 + o2])));
                    atomicAdd(&ag[o2], m1);
                }
            }
        }
        grid_sync();

        // ===== Phase F: out = agg*invd + root + bias; BN stats =====
        {
            int o = tid & 63, r = tid >> 6;
            float asum = 0.0f, asq = 0.0f;
            const float* cbl = cb + l * CONV;
            if (o < CONV) {
                float cbo = cbl[o];
                for (int nb = blockIdx.x * 4; nb < N; nb += gridDim.x * 4) {
                    int n = nb + r;
                    if (n < N) {
                        float v = fmaf(aggNew[n * CONV + o], g_invd[n],
                                       g_P[(long)n * PDIM + 196 + o] + cbo);
                        aggNew[n * CONV + o] = v;   // pre-BN
                        asum += v; asq += v * v;
                    }
                }
            }
            __syncthreads();          // smem reuse barrier
            sw[tid] = asum; sw[256 + tid] = asq;
            __syncthreads();
            if (tid < 64) {
                float s = sw[tid] + sw[tid + 64] + sw[tid + 128] + sw[tid + 192];
                float q = sw[256 + tid] + sw[256 + tid + 64] + sw[256 + tid + 128] + sw[256 + tid + 192];
                if (tid < CONV) {
                    atomicAdd(&statsNew[tid], s);
                    atomicAdd(&statsNew[CONV + tid], q);
                }
            }
        }
        grid_sync();
    }

    // ===== Phase H: final layer-2 BN+lrelu -> JK =====
    {
        float* statsNew = g_stats + (2 & 1) * 98;   // stats0
        if (tid < CONV) {
            float invN = 1.0f / (float)N;
            float mu  = statsNew[tid] * invN;
            float var = statsNew[CONV + tid] * invN - mu * mu;
            float sc  = gam[2 * CONV + tid] * rsqrtf(var + 1e-5f);
            sbn[tid]        = sc;
            sbn[CONV + tid] = bet[2 * CONV + tid] - mu * sc;
        }
        __syncthreads();
        float* aggNew = g_aggA;                     // layer 2 is even
        int o = tid & 63, r = tid >> 6;
        if (o < CONV) {
            for (int nb = blockIdx.x * 4; nb < N; nb += gridDim.x * 4) {
                int n = nb + r;
                if (n < N) {
                    float y = aggNew[n * CONV + o] * sbn[o] + sbn[CONV + o];
                    y = LRELU(y);
                    jk[n * CONV + o] += y;
                }
            }
        }
    }
}

// ---------------------------------------------------------------------------
extern "C" void kernel_launch(void* const* d_in, const int* in_sizes, int n_in,
                              void* d_out, int out_size)
{
    const float* x     = (const float*)d_in[0];
    const void*  ei    = d_in[1];
    const float* ea    = (const float*)d_in[2];
    const float* lin_w = (const float*)d_in[3];
    const float* lin_b = (const float*)d_in[4];
    const float* w1    = (const float*)d_in[5];
    const float* b1    = (const float*)d_in[6];
    const float* w2    = (const float*)d_in[7];
    const float* b2    = (const float*)d_in[8];
    const float* rw    = (const float*)d_in[9];
    const float* cb    = (const float*)d_in[10];
    const float* gam   = (const float*)d_in[11];
    const float* bet   = (const float*)d_in[12];
    float* jk = (float*)d_out;

    int N = in_sizes[0] / 56;
    int E = in_sizes[2] / 10;

    const int smemBytes = SMEM_FLOATS * sizeof(float);   // ~54.7 KB
    cudaFuncSetAttribute(k_fused, cudaFuncAttributeMaxDynamicSharedMemorySize, smemBytes);

    int dev = 0, nsm = 148;
    cudaGetDevice(&dev);
    cudaDeviceGetAttribute(&nsm, cudaDevAttrMultiProcessorCount, dev);
    int occ = 1;
    cudaOccupancyMaxActiveBlocksPerMultiprocessor(&occ, k_fused, TPB, smemBytes);
    if (occ < 1) occ = 1;
    if (occ > 2) occ = 2;          // 2 blocks/SM is enough parallelism
    int grid = nsm * occ;

    k_fused<<<grid, TPB, smemBytes>>>(x, ei, ea, lin_w, lin_b, w1, b1,
                                      w2, b2, rw, cb, gam, bet, jk, N, E);
}

// round 4
// speedup vs baseline: 1.2191x; 1.1556x over previous
#include <cuda_runtime.h>
#include <cuda_bf16.h>

#define TPB    256
#define CONV   49
#define PDIM   245          // 5*49: [W2_0 | W2_1 | W2_2 | B2 | root_w]
#define MAXN   25000
#define MAXE   50000
#define NTILE  16
#define LRELU(v) ((v) > 0.0f ? (v) : 0.01f * (v))

// smem floats: sw[49*245] | sh[16*49] | sbn[98]   (~51.5 KB)
#define SMEM_FLOATS (49 * PDIM + NTILE * CONV + 2 * CONV)

// ---------------- device scratch ----------------
__device__ float g_hcA [MAXN * CONV];
__device__ float g_P   [MAXN * PDIM];
__device__ float g_aggA[MAXN * CONV];
__device__ float g_aggB[MAXN * CONV];
__device__ float g_invd[MAXN];
__device__ float g_stats[2 * 2 * CONV];
__device__ int   g_src[MAXE];
__device__ int   g_dst[MAXE];
__device__ int   g_is64;
__device__ unsigned g_bar_count = 0;
__device__ unsigned g_bar_gen   = 0;

__device__ __forceinline__ void grid_sync() {
    __syncthreads();
    if (threadIdx.x == 0) {
        __threadfence();
        unsigned gen = *(volatile unsigned*)&g_bar_gen;
        unsigned t = atomicAdd(&g_bar_count, 1u);
        if (t == gridDim.x - 1) {
            g_bar_count = 0;
            __threadfence();
            *(volatile unsigned*)&g_bar_gen = gen + 1;
        } else {
            while (*(volatile unsigned*)&g_bar_gen == gen) __nanosleep(32);
        }
        __threadfence();
    }
    __syncthreads();
}

__global__ __launch_bounds__(TPB, 4) void k_fused(
    const float* __restrict__ x, const void* __restrict__ ei,
    const float* __restrict__ ea,
    const float* __restrict__ lin_w, const float* __restrict__ lin_b,
    const float* __restrict__ w1,  const float* __restrict__ b1,
    const float* __restrict__ w2,  const float* __restrict__ b2,
    const float* __restrict__ rw,  const float* __restrict__ cb,
    const float* __restrict__ gam, const float* __restrict__ bet,
    float* __restrict__ jk, int N, int E)
{
    extern __shared__ float smem[];
    float* sw  = smem;
    float* sh  = smem + 49 * PDIM;
    float* sbn = sh + NTILE * CONV;

    const int tid  = threadIdx.x;
    const int gtid = blockIdx.x * TPB + tid;
    const int gsz  = gridDim.x * TPB;

    // ===== Phase A: dtype sniff + zero degree =====
    {
        int local_ok = 1;
        if (blockIdx.x == 0) {
            const int* w = (const int*)ei;
            int nv = (E < 1024) ? E : 1024;
            for (int i = tid; i < nv; i += TPB)
                if (w[2 * i + 1] != 0) local_ok = 0;
        }
        int all_ok = __syncthreads_and(local_ok);
        if (blockIdx.x == 0 && tid == 0) g_is64 = all_ok;
        for (int n = gtid; n < N; n += gsz) g_invd[n] = 0.0f;
    }
    grid_sync();

    // ===== Phase B: decode edges + degree =====
    {
        if (g_is64) {
            const long long* p = (const long long*)ei;
            for (int e = gtid; e < E; e += gsz) {
                int s = (int)p[e], d = (int)p[E + e];
                g_src[e] = s; g_dst[e] = d;
                atomicAdd(&g_invd[d], 1.0f);
            }
        } else {
            const int* p = (const int*)ei;
            for (int e = gtid; e < E; e += gsz) {
                int s = p[e], d = p[E + e];
                g_src[e] = s; g_dst[e] = d;
                atomicAdd(&g_invd[d], 1.0f);
            }
        }
    }
    grid_sync();

    // ===== Phase C: invd + input projection =====
    {
        for (int n = gtid; n < N; n += gsz)
            g_invd[n] = 1.0f / fmaxf(g_invd[n], 1.0f);
        for (int i = tid; i < 56 * CONV; i += TPB) sw[i] = lin_w[i];
        __syncthreads();
        int o = tid & 63, r = tid >> 6;
        for (int nb = blockIdx.x * 4; nb < N; nb += gridDim.x * 4) {
            int n = nb + r;
            if (n < N && o < CONV) {
                const float* xr = x + (long)n * 56;
                float acc = lin_b[o];
                #pragma unroll
                for (int i = 0; i < 56; i++)
                    acc = fmaf(xr[i], sw[i * CONV + o], acc);
                acc = LRELU(acc);
                g_hcA[n * CONV + o] = acc;
                jk[n * CONV + o]   = acc;
            }
        }
    }
    grid_sync();

    const int TILES = (N + NTILE - 1) / NTILE;

    for (int l = 0; l < 3; l++) {
        float* aggNew   = (l & 1) ? g_aggB : g_aggA;
        float* aggOld   = (l & 1) ? g_aggA : g_aggB;
        float* statsNew = g_stats + (l & 1) * 98;
        float* statsOld = g_stats + ((l + 1) & 1) * 98;
        const float* w2l = w2 + (long)l * 3 * 2401;
        const float* b2l = b2 + (long)l * 2401;
        const float* rwl = rw + (long)l * 2401;

        // ===== Phase D: P-GEMM (fused BN+lrelu+JK on tile load) =====
        {
            for (int idx = tid; idx < 49 * PDIM; idx += TPB) {
                int i = idx / PDIM, j = idx % PDIM;
                int m = j / CONV, o = j % CONV;
                float v;
                if (m < 3)       v = w2l[m * 2401 + i * CONV + o];
                else if (m == 3) v = b2l[i * CONV + o];
                else             v = rwl[i * CONV + o];
                sw[idx] = v;
            }
            if (l > 0 && tid < CONV) {
                float invN = 1.0f / (float)N;
                float mu  = statsOld[tid] * invN;
                float var = statsOld[CONV + tid] * invN - mu * mu;
                float sc  = gam[(l - 1) * CONV + tid] * rsqrtf(var + 1e-5f);
                sbn[tid]        = sc;
                sbn[CONV + tid] = bet[(l - 1) * CONV + tid] - mu * sc;
            }
            if (blockIdx.x == 0 && tid < 98) statsNew[tid] = 0.0f;
            for (int i = gtid; i < N * CONV; i += gsz) aggNew[i] = 0.0f;
            __syncthreads();

            const int jg = tid & 63;            // 4 cols: jg, +64, +128, +192
            const int yg = tid >> 6;            // 4 rows: yg*4 .. +3
            const int ybase = yg * 4;
            const bool has3 = (jg + 192 < PDIM);

            for (int tile = blockIdx.x; tile < TILES; tile += gridDim.x) {
                int nb = tile * NTILE;
                for (int idx = tid; idx < NTILE * CONV; idx += TPB) {
                    int ln = idx / CONV, i = idx % CONV;
                    int n = nb + ln;
                    float y = 0.0f;
                    if (n < N) {
                        if (l == 0) {
                            y = g_hcA[n * CONV + i];
                        } else {
                            float pre = aggOld[n * CONV + i];
                            y = pre * sbn[i] + sbn[CONV + i];
                            y = LRELU(y);
                            jk[n * CONV + i] += y;
                        }
                    }
                    sh[idx] = y;
                }
                __syncthreads();

                float acc[4][4];
                #pragma unroll
                for (int y = 0; y < 4; y++)
                    #pragma unroll
                    for (int j = 0; j < 4; j++) acc[y][j] = 0.0f;

                #pragma unroll 7
                for (int i = 0; i < CONV; i++) {
                    const float* swi = sw + i * PDIM + jg;
                    float w0 = swi[0];
                    float w1 = swi[64];
                    float w2v = swi[128];
                    float w3 = has3 ? swi[192] : 0.0f;
                    #pragma unroll
                    for (int y = 0; y < 4; y++) {
                        float hv = sh[(ybase + y) * CONV + i];
                        acc[y][0] = fmaf(hv, w0,  acc[y][0]);
                        acc[y][1] = fmaf(hv, w1,  acc[y][1]);
                        acc[y][2] = fmaf(hv, w2v, acc[y][2]);
                        acc[y][3] = fmaf(hv, w3,  acc[y][3]);
                    }
                }
                #pragma unroll
                for (int y = 0; y < 4; y++) {
                    int n = nb + ybase + y;
                    if (n < N) {
                        float* Pr = g_P + (long)n * PDIM + jg;
                        Pr[0]   = acc[y][0];
                        Pr[64]  = acc[y][1];
                        Pr[128] = acc[y][2];
                        if (has3) Pr[192] = acc[y][3];
                    }
                }
                __syncthreads();
            }
        }
        grid_sync();

        // ===== Phase E: edge messages + scatter =====
        {
            if (tid < 30) sw[tid] = w1[l * 30 + tid];
            if (tid < 3)  sw[32 + tid] = b1[l * 3 + tid];
            __syncthreads();
            int warp = (blockIdx.x * TPB + tid) >> 5;
            int lane = tid & 31;
            int nwarp = gsz >> 5;
            for (int e = warp; e < E; e += nwarp) {
                int src = g_src[e], dst = g_dst[e];
                const float* a = ea + (long)e * 10;
                float t0 = sw[32], t1 = sw[33], t2 = sw[34];
                #pragma unroll
                for (int i = 0; i < 10; i++) {
                    float v = a[i];
                    t0 = fmaf(v, sw[i * 3 + 0], t0);
                    t1 = fmaf(v, sw[i * 3 + 1], t1);
                    t2 = fmaf(v, sw[i * 3 + 2], t2);
                }
                t0 = fmaxf(t0, 0.0f); t1 = fmaxf(t1, 0.0f); t2 = fmaxf(t2, 0.0f);
                const float* Ps = g_P + (long)src * PDIM;
                float* ag = aggNew + (long)dst * CONV;
                float m0 = fmaf(t0, Ps[lane],
                           fmaf(t1, Ps[49 + lane],
                           fmaf(t2, Ps[98 + lane], Ps[147 + lane])));
                atomicAdd(&ag[lane], m0);
                int o2 = lane + 32;
                if (o2 < CONV) {
                    float m1 = fmaf(t0, Ps[o2],
                               fmaf(t1, Ps[49 + o2],
                               fmaf(t2, Ps[98 + o2], Ps[147 + o2])));
                    atomicAdd(&ag[o2], m1);
                }
            }
        }
        grid_sync();

        // ===== Phase F: out = agg*invd + root + bias; BN stats =====
        {
            int o = tid & 63, r = tid >> 6;
            float asum = 0.0f, asq = 0.0f;
            const float* cbl = cb + l * CONV;
            if (o < CONV) {
                float cbo = cbl[o];
                for (int nb = blockIdx.x * 4; nb < N; nb += gridDim.x * 4) {
                    int n = nb + r;
                    if (n < N) {
                        float v = fmaf(aggNew[n * CONV + o], g_invd[n],
                                       g_P[(long)n * PDIM + 196 + o] + cbo);
                        aggNew[n * CONV + o] = v;
                        asum += v; asq += v * v;
                    }
                }
            }
            __syncthreads();
            sw[tid] = asum; sw[256 + tid] = asq;
            __syncthreads();
            if (tid < 64) {
                float s = sw[tid] + sw[tid + 64] + sw[tid + 128] + sw[tid + 192];
                float q = sw[256 + tid] + sw[256 + tid + 64] + sw[256 + tid + 128] + sw[256 + tid + 192];
                if (tid < CONV) {
                    atomicAdd(&statsNew[tid], s);
                    atomicAdd(&statsNew[CONV + tid], q);
                }
            }
        }
        grid_sync();
    }

    // ===== Final layer-2 BN+lrelu -> JK =====
    {
        float* statsNew = g_stats;       // layer 2 (even) stats
        if (tid < CONV) {
            float invN = 1.0f / (float)N;
            float mu  = statsNew[tid] * invN;
            float var = statsNew[CONV + tid] * invN - mu * mu;
            float sc  = gam[2 * CONV + tid] * rsqrtf(var + 1e-5f);
            sbn[tid]        = sc;
            sbn[CONV + tid] = bet[2 * CONV + tid] - mu * sc;
        }
        __syncthreads();
        float* aggNew = g_aggA;
        int o = tid & 63, r = tid >> 6;
        if (o < CONV) {
            for (int nb = blockIdx.x * 4; nb < N; nb += gridDim.x * 4) {
                int n = nb + r;
                if (n < N) {
                    float y = aggNew[n * CONV + o] * sbn[o] + sbn[CONV + o];
                    y = LRELU(y);
                    jk[n * CONV + o] += y;
                }
            }
        }
    }
}

// ---------------------------------------------------------------------------
extern "C" void kernel_launch(void* const* d_in, const int* in_sizes, int n_in,
                              void* d_out, int out_size)
{
    const float* x     = (const float*)d_in[0];
    const void*  ei    = d_in[1];
    const float* ea    = (const float*)d_in[2];
    const float* lin_w = (const float*)d_in[3];
    const float* lin_b = (const float*)d_in[4];
    const float* w1    = (const float*)d_in[5];
    const float* b1    = (const float*)d_in[6];
    const float* w2    = (const float*)d_in[7];
    const float* b2    = (const float*)d_in[8];
    const float* rw    = (const float*)d_in[9];
    const float* cb    = (const float*)d_in[10];
    const float* gam   = (const float*)d_in[11];
    const float* bet   = (const float*)d_in[12];
    float* jk = (float*)d_out;

    int N = in_sizes[0] / 56;
    int E = in_sizes[2] / 10;

    const int smemBytes = SMEM_FLOATS * sizeof(float);
    cudaFuncSetAttribute(k_fused, cudaFuncAttributeMaxDynamicSharedMemorySize, smemBytes);

    int dev = 0, nsm = 148;
    cudaGetDevice(&dev);
    cudaDeviceGetAttribute(&nsm, cudaDevAttrMultiProcessorCount, dev);
    int occ = 1;
    cudaOccupancyMaxActiveBlocksPerMultiprocessor(&occ, k_fused, TPB, smemBytes);
    if (occ < 1) occ = 1;
    if (occ > 4) occ = 4;
    int grid = nsm * occ;

    k_fused<<<grid, TPB, smemBytes>>>(x, ei, ea, lin_w, lin_b, w1, b1,
                                      w2, b2, rw, cb, gam, bet, jk, N, E);
}